// round 5
// baseline (speedup 1.0000x reference)
#include <cuda_runtime.h>
#include <math.h>
#include <stdint.h>

// ---------------- problem constants ----------------
#define BB 64
#define TT 256
#define EE 300
#define HH 256
#define G4 1024          // 4*H
#define NLBL 17
#define LTOT 19
#define START_LBL 17
#define END_LBL 18
#define LOW_POT (-10000.0f)

typedef unsigned long long u64;

// ---------------- packed f32x2 helpers (Blackwell, .b64 regs) ----------------
__device__ __forceinline__ u64 fdup(float x) {
    u64 r; asm("mov.b64 %0,{%1,%1};" : "=l"(r) : "f"(x)); return r;
}
__device__ __forceinline__ void fma2(u64& a, u64 m, u64 b) {
    asm("fma.rn.f32x2 %0,%1,%2,%0;" : "+l"(a) : "l"(m), "l"(b));
}
__device__ __forceinline__ void add2(u64& a, u64 b) {
    asm("add.rn.f32x2 %0,%0,%1;" : "+l"(a) : "l"(b));
}
__device__ __forceinline__ float2 f2lo(u64 v) {
    float2 r; asm("mov.b64 {%0,%1},%2;" : "=f"(r.x), "=f"(r.y) : "l"(v)); return r;
}
__device__ __forceinline__ u64 fpack(float a, float b) {
    u64 r; asm("mov.b64 %0,{%1,%2};" : "=l"(r) : "f"(a), "f"(b)); return r;
}

// ---------------- cluster helpers ----------------
__device__ __forceinline__ uint32_t s2u(const void* p) {
    uint32_t a;
    asm("{ .reg .u64 t; cvta.to.shared.u64 t, %1; cvt.u32.u64 %0, t; }" : "=r"(a) : "l"(p));
    return a;
}
__device__ __forceinline__ uint32_t ctarank() {
    uint32_t r; asm("mov.u32 %0, %%cluster_ctarank;" : "=r"(r)); return r;
}
__device__ __forceinline__ void st_cluster_u64(uint32_t saddr, uint32_t rank, u64 v) {
    uint32_t ra;
    asm("mapa.shared::cluster.u32 %0, %1, %2;" : "=r"(ra) : "r"(saddr), "r"(rank));
    asm volatile("st.shared::cluster.b64 [%0], %1;" :: "r"(ra), "l"(v));
}
#define CLUSTER_SYNC() do { \
    asm volatile("barrier.cluster.arrive.aligned;" ::: "memory"); \
    asm volatile("barrier.cluster.wait.aligned;" ::: "memory"); \
} while (0)

// ---------------- device scratch ----------------
__device__ float g_xproj[(size_t)BB * TT * 2 * G4];   // [bt][2048] fwd 0..1023, bwd 1024..2047 (bias folded)
__device__ float g_hall[(size_t)BB * TT * 2 * HH];    // [bt][512] concat(h_f, h_b)
__device__ float g_unary[(size_t)BB * TT * NLBL];     // [bt][17]

__device__ __forceinline__ float sigf(float x) { return 1.0f / (1.0f + expf(-x)); }

// ---------------- kernel 1: embedding gather + x_proj GEMM ----------------
// 128x128 tile, 8x8 micro-tile via f32x2, k-tile 20 (300 = 15*20)
__global__ void k_xproj(const int* __restrict__ x, const float* __restrict__ emb,
                        const float* __restrict__ Wf, const float* __restrict__ Wb,
                        const float* __restrict__ bf, const float* __restrict__ bb) {
    __shared__ float As[20][128];
    __shared__ float Bs[20][128];
    __shared__ int toks[128];
    const int tid = threadIdx.x;
    const int m0 = blockIdx.y * 128;
    const int n0 = blockIdx.x * 128;
    const int tx = tid & 15;
    const int ty = tid >> 4;

    if (tid < 128) toks[tid] = x[m0 + tid];

    u64 acc2[8][4];
#pragma unroll
    for (int i = 0; i < 8; i++)
#pragma unroll
        for (int j = 0; j < 4; j++) acc2[i][j] = 0ull;
    __syncthreads();

    for (int k0 = 0; k0 < EE; k0 += 20) {
#pragma unroll
        for (int l = tid; l < 640; l += 256) {
            int kq = l >> 7, r = l & 127;
            float4 v = *(const float4*)&emb[(size_t)toks[r] * EE + k0 + kq * 4];
            As[kq * 4 + 0][r] = v.x; As[kq * 4 + 1][r] = v.y;
            As[kq * 4 + 2][r] = v.z; As[kq * 4 + 3][r] = v.w;
        }
#pragma unroll
        for (int l = tid; l < 640; l += 256) {
            int kq = l >> 7, r = l & 127;
            int g = n0 + r;
            const float* Wp = (g < G4) ? &Wf[(size_t)g * EE] : &Wb[(size_t)(g - G4) * EE];
            float4 v = *(const float4*)&Wp[k0 + kq * 4];
            Bs[kq * 4 + 0][r] = v.x; Bs[kq * 4 + 1][r] = v.y;
            Bs[kq * 4 + 2][r] = v.z; Bs[kq * 4 + 3][r] = v.w;
        }
        __syncthreads();
#pragma unroll
        for (int kk = 0; kk < 20; kk++) {
            float4 a0 = *(const float4*)&As[kk][ty * 8];
            float4 a1 = *(const float4*)&As[kk][ty * 8 + 4];
            ulonglong2 b01 = *(const ulonglong2*)&Bs[kk][tx * 8];
            ulonglong2 b23 = *(const ulonglong2*)&Bs[kk][tx * 8 + 4];
            float av[8] = {a0.x, a0.y, a0.z, a0.w, a1.x, a1.y, a1.z, a1.w};
#pragma unroll
            for (int i = 0; i < 8; i++) {
                u64 ad = fdup(av[i]);
                fma2(acc2[i][0], ad, b01.x);
                fma2(acc2[i][1], ad, b01.y);
                fma2(acc2[i][2], ad, b23.x);
                fma2(acc2[i][3], ad, b23.y);
            }
        }
        __syncthreads();
    }

    const int gc = n0 + tx * 8;
    float bias[8];
#pragma unroll
    for (int j = 0; j < 8; j++) {
        int g = gc + j;
        bias[j] = (g < G4) ? bf[g] : bb[g - G4];
    }
#pragma unroll
    for (int i = 0; i < 8; i++) {
        int row = m0 + ty * 8 + i;
        float2 p0 = f2lo(acc2[i][0]);
        float2 p1 = f2lo(acc2[i][1]);
        float2 p2 = f2lo(acc2[i][2]);
        float2 p3 = f2lo(acc2[i][3]);
        float4 v0 = make_float4(p0.x + bias[0], p0.y + bias[1], p1.x + bias[2], p1.y + bias[3]);
        float4 v1 = make_float4(p2.x + bias[4], p2.y + bias[5], p3.x + bias[6], p3.y + bias[7]);
        *(float4*)(&g_xproj[(size_t)row * 2048 + gc]) = v0;
        *(float4*)(&g_xproj[(size_t)row * 2048 + gc + 4]) = v1;
    }
}

// ---------------- kernel 2: cluster-DSMEM bidirectional LSTM ----------------
// 16 clusters of 8 CTAs (grid 128). Cluster ci: dir = ci>>3, batches [8*(ci&7), +8).
// CTA rank r holds W_hh slice for hidden units [32r, 32r+32) (128 gate cols,
// 128KB) resident in SMEM for the whole kernel. Per step: local GEMV -> SMEM
// k-reduction -> cell update -> push own h units into all 8 peers' SMEM via
// st.shared::cluster -> cluster.sync. No global traffic for W or h.
// SMEM floats: Ws 33792 ([k][132] padded), hbuf 2*2048 ([buf][u][b]),
// red 8192 (8 k-groups * 512 u64), gs 1024 ([c][b]).
#define LSTM_SMEM_BYTES ((33792 + 4096 + 8192 + 1024) * 4)
__global__ void __cluster_dims__(8, 1, 1) __launch_bounds__(256, 1)
k_lstm(const float* __restrict__ Whf, const float* __restrict__ Whb) {
    extern __shared__ float sm[];
    float* Ws   = sm;                      // [256][132]
    float* hbuf = sm + 33792;              // [2][256][8]
    u64*   red  = (u64*)(sm + 37888);      // [8][512]
    float* gs   = sm + 46080;              // [128][8]

    const int tid = threadIdx.x;
    const uint32_t rank = ctarank();
    const int cidx = blockIdx.x >> 3;
    const int d = cidx >> 3;
    const int B0 = (cidx & 7) * 8;
    const float* Wh = d ? Whb : Whf;

    // load W slice: Ws[k*132 + c] = Wh[(s*256 + 32*rank + uu)*256 + k], c = s*32+uu
    for (int idx = tid; idx < 32768; idx += 256) {
        int c = idx >> 8, k = idx & 255;
        int s = c >> 5, uu = c & 31;
        Ws[k * 132 + c] = Wh[(size_t)((s << 8) + (rank << 5) + uu) * HH + k];
    }
    // zero h buffer 0 only (buffer 1 is fully written by peers during step 0)
    for (int i = tid; i < 2048; i += 256) hbuf[i] = 0.0f;
    __syncthreads();

    // GEMV role: warp kg owns k range [32kg, 32kg+32); lane owns 4 cols c4..c4+3
    const int kg = tid >> 5;
    const int kbeg = kg * 32;
    const int c4 = (tid & 31) * 4;

    // reduce role: 2 packed outputs (col, batch-pair)
    const int oid0 = tid * 2, oid1 = tid * 2 + 1;
    const int cA = oid0 >> 2, bpA = oid0 & 3;
    const int cB = oid1 >> 2, bpB = oid1 & 3;
    const int gcolA = (cA >> 5) * 256 + rank * 32 + (cA & 31);
    const int gcolB = (cB >> 5) * 256 + rank * 32 + (cB & 31);
    const float* pxA0 = g_xproj + (size_t)(B0 + 2 * bpA + 0) * TT * 2048 + d * G4 + gcolA;
    const float* pxA1 = g_xproj + (size_t)(B0 + 2 * bpA + 1) * TT * 2048 + d * G4 + gcolA;
    const float* pxB0 = g_xproj + (size_t)(B0 + 2 * bpB + 0) * TT * 2048 + d * G4 + gcolB;
    const float* pxB1 = g_xproj + (size_t)(B0 + 2 * bpB + 1) * TT * 2048 + d * G4 + gcolB;

    // cell role (tid<128): unit ul = tid>>2, batch pair bp = tid&3
    const int ul = tid >> 2;
    const int cbp = tid & 3;
    const int bl = cbp * 2;
    const uint32_t h_u32 = s2u(hbuf);
    float cst0 = 0.0f, cst1 = 0.0f;

    int cur = 0;
    for (int step = 0; step < TT; step++) {
        const int t = d ? (TT - 1 - step) : step;

        // prefetch x-projection (used ~2000 cycles later in reduce)
        float xA0 = __ldcg(pxA0 + (size_t)t * 2048);
        float xA1 = __ldcg(pxA1 + (size_t)t * 2048);
        float xB0 = __ldcg(pxB0 + (size_t)t * 2048);
        float xB1 = __ldcg(pxB1 + (size_t)t * 2048);

        // GEMV partial: 8 batches x 4 cols over this warp's k range
        u64 acc[4][4];
#pragma unroll
        for (int bp = 0; bp < 4; bp++)
#pragma unroll
            for (int ci = 0; ci < 4; ci++) acc[bp][ci] = 0ull;
        const float* hc = hbuf + cur * 2048;
#pragma unroll 8
        for (int k = kbeg; k < kbeg + 32; k++) {
            ulonglong2 h01 = *(const ulonglong2*)(hc + k * 8);
            ulonglong2 h23 = *(const ulonglong2*)(hc + k * 8 + 4);
            float4 w4 = *(const float4*)(Ws + k * 132 + c4);
            u64 w0 = fdup(w4.x), w1 = fdup(w4.y), w2 = fdup(w4.z), w3 = fdup(w4.w);
            fma2(acc[0][0], h01.x, w0); fma2(acc[0][1], h01.x, w1);
            fma2(acc[0][2], h01.x, w2); fma2(acc[0][3], h01.x, w3);
            fma2(acc[1][0], h01.y, w0); fma2(acc[1][1], h01.y, w1);
            fma2(acc[1][2], h01.y, w2); fma2(acc[1][3], h01.y, w3);
            fma2(acc[2][0], h23.x, w0); fma2(acc[2][1], h23.x, w1);
            fma2(acc[2][2], h23.x, w2); fma2(acc[2][3], h23.x, w3);
            fma2(acc[3][0], h23.y, w0); fma2(acc[3][1], h23.y, w1);
            fma2(acc[3][2], h23.y, w2); fma2(acc[3][3], h23.y, w3);
        }
#pragma unroll
        for (int ci = 0; ci < 4; ci++)
#pragma unroll
            for (int bp = 0; bp < 4; bp++)
                red[kg * 512 + (c4 + ci) * 4 + bp] = acc[bp][ci];
        __syncthreads();

        // reduce 8 k-group partials + add x-projection -> gate pre-activations
        {
            u64 s0 = red[oid0];
            u64 s1 = red[oid1];
#pragma unroll
            for (int g2 = 1; g2 < 8; g2++) {
                add2(s0, red[g2 * 512 + oid0]);
                add2(s1, red[g2 * 512 + oid1]);
            }
            float2 f0 = f2lo(s0), f1 = f2lo(s1);
            gs[cA * 8 + 2 * bpA + 0] = f0.x + xA0;
            gs[cA * 8 + 2 * bpA + 1] = f0.y + xA1;
            gs[cB * 8 + 2 * bpB + 0] = f1.x + xB0;
            gs[cB * 8 + 2 * bpB + 1] = f1.y + xB1;
        }
        __syncthreads();

        // cell update + DSMEM broadcast of h to all cluster CTAs
        if (tid < 128) {
            float i0 = gs[(0 * 32 + ul) * 8 + bl], i1 = gs[(0 * 32 + ul) * 8 + bl + 1];
            float f0 = gs[(1 * 32 + ul) * 8 + bl], f1 = gs[(1 * 32 + ul) * 8 + bl + 1];
            float g0 = gs[(2 * 32 + ul) * 8 + bl], g1 = gs[(2 * 32 + ul) * 8 + bl + 1];
            float o0 = gs[(3 * 32 + ul) * 8 + bl], o1 = gs[(3 * 32 + ul) * 8 + bl + 1];
            cst0 = sigf(f0) * cst0 + sigf(i0) * tanhf(g0);
            cst1 = sigf(f1) * cst1 + sigf(i1) * tanhf(g1);
            float h0 = sigf(o0) * tanhf(cst0);
            float h1 = sigf(o1) * tanhf(cst1);
            u64 hp = fpack(h0, h1);
            int ug = rank * 32 + ul;
            uint32_t hoff = h_u32 + (uint32_t)(((cur ^ 1) * 2048 + ug * 8 + bl) * 4);
#pragma unroll
            for (uint32_t r = 0; r < 8; r++) st_cluster_u64(hoff, r, hp);
            g_hall[((size_t)(B0 + bl + 0) * TT + t) * 512 + d * HH + ug] = h0;
            g_hall[((size_t)(B0 + bl + 1) * TT + t) * 512 + d * HH + ug] = h1;
        }
        CLUSTER_SYNC();
        cur ^= 1;
    }
}

// ---------------- kernel 3: fused fc1(relu) + classifier ----------------
#define FC_SMEM_FLOATS (128 * 130)
__global__ void k_fc(const float* __restrict__ fc1W, const float* __restrict__ fc1b,
                     const float* __restrict__ clsW, const float* __restrict__ clsb) {
    __shared__ float As[16][128];
    __shared__ float Bs[16][128];
    extern __shared__ float inter[];   // [128][130]
    const int tid = threadIdx.x;
    const int m0 = blockIdx.x * 128;
    const int tr = tid >> 4;
    const int tc = tid & 15;

    u64 acc2[8][4];
#pragma unroll
    for (int i = 0; i < 8; i++)
#pragma unroll
        for (int jj = 0; jj < 4; jj++) acc2[i][jj] = 0ull;

    for (int k0 = 0; k0 < 512; k0 += 16) {
#pragma unroll
        for (int l = tid; l < 512; l += 256) {
            int kq = l >> 7, r = l & 127;
            float4 v = *(const float4*)&g_hall[(size_t)(m0 + r) * 512 + k0 + kq * 4];
            As[kq * 4 + 0][r] = v.x; As[kq * 4 + 1][r] = v.y;
            As[kq * 4 + 2][r] = v.z; As[kq * 4 + 3][r] = v.w;
        }
#pragma unroll
        for (int l = tid; l < 512; l += 256) {
            int kq = l >> 7, r = l & 127;
            float4 v = *(const float4*)&fc1W[(size_t)r * 512 + k0 + kq * 4];
            Bs[kq * 4 + 0][r] = v.x; Bs[kq * 4 + 1][r] = v.y;
            Bs[kq * 4 + 2][r] = v.z; Bs[kq * 4 + 3][r] = v.w;
        }
        __syncthreads();
#pragma unroll
        for (int kk = 0; kk < 16; kk++) {
            float4 a0 = *(const float4*)&As[kk][tr * 8];
            float4 a1 = *(const float4*)&As[kk][tr * 8 + 4];
            ulonglong2 b01 = *(const ulonglong2*)&Bs[kk][tc * 8];
            ulonglong2 b23 = *(const ulonglong2*)&Bs[kk][tc * 8 + 4];
            float av[8] = {a0.x, a0.y, a0.z, a0.w, a1.x, a1.y, a1.z, a1.w};
#pragma unroll
            for (int i = 0; i < 8; i++) {
                u64 ad = fdup(av[i]);
                fma2(acc2[i][0], ad, b01.x);
                fma2(acc2[i][1], ad, b01.y);
                fma2(acc2[i][2], ad, b23.x);
                fma2(acc2[i][3], ad, b23.y);
            }
        }
        __syncthreads();
    }
#pragma unroll
    for (int i = 0; i < 8; i++) {
        int r = tr * 8 + i;
#pragma unroll
        for (int jj = 0; jj < 4; jj++) {
            int n = tc * 8 + jj * 2;
            float2 p = f2lo(acc2[i][jj]);
            float v0 = p.x + fc1b[n];
            float v1 = p.y + fc1b[n + 1];
            inter[r * 130 + n]     = v0 > 0.0f ? v0 : 0.0f;
            inter[r * 130 + n + 1] = v1 > 0.0f ? v1 : 0.0f;
        }
    }
    __syncthreads();

    for (int idx = tid; idx < 128 * NLBL; idx += 256) {
        int r = idx / NLBL, lab = idx - r * NLBL;
        const u64* w2 = (const u64*)(clsW + (size_t)lab * 128);
        const u64* i2 = (const u64*)(inter + r * 130);
        u64 s2 = 0ull;
#pragma unroll 8
        for (int k = 0; k < 64; k++) fma2(s2, i2[k], w2[k]);
        float2 p = f2lo(s2);
        g_unary[(size_t)(m0 + r) * NLBL + lab] = clsb[lab] + p.x + p.y;
    }
}

// ---------------- kernel 4: Viterbi decode, one block per batch ----------------
__global__ void k_viterbi(const float* __restrict__ trans, float* __restrict__ out) {
    const int b = blockIdx.x;
    const int tid = threadIdx.x;
    __shared__ float tr[LTOT * LTOT];
    __shared__ float sc[2][LTOT];
    __shared__ unsigned char bp[TT][LTOT];

    for (int l = tid; l < LTOT * LTOT; l += 32) tr[l] = trans[l];
    if (tid < LTOT) sc[0][tid] = (tid == START_LBL) ? 0.0f : LOW_POT;
    __syncwarp();

    const float* un = g_unary + (size_t)b * TT * NLBL;
    for (int t = 0; t < TT; t++) {
        const int cur = t & 1, nxt = cur ^ 1;
        if (tid < LTOT) {
            const int jl = tid;
            float best = -3.4e38f;
            int bi = 0;
#pragma unroll
            for (int p = 0; p < LTOT; p++) {
                float v = sc[cur][p] + tr[jl * LTOT + p];
                if (v > best) { best = v; bi = p; }
            }
            float u = (jl < NLBL) ? un[t * NLBL + jl] : LOW_POT;
            sc[nxt][jl] = best + u;
            bp[t][jl] = (unsigned char)bi;
        }
        __syncwarp();
    }
    if (tid == 0) {
        float best = -3.4e38f;
        int bi = 0;
        for (int jl = 0; jl < LTOT; jl++) {
            float v = sc[0][jl] + tr[END_LBL * LTOT + jl];
            if (v > best) { best = v; bi = jl; }
        }
        out[b] = best;
        int lab = bi;
        for (int t = TT - 1; t >= 0; t--) {
            out[BB + b * TT + t] = (float)lab;
            lab = bp[t][lab];
        }
    }
}

// ---------------- launch ----------------
extern "C" void kernel_launch(void* const* d_in, const int* in_sizes, int n_in,
                              void* d_out, int out_size) {
    const int*   x     = (const int*)d_in[0];
    const float* emb   = (const float*)d_in[1];
    const float* Wihf  = (const float*)d_in[2];
    const float* Whhf  = (const float*)d_in[3];
    const float* bf    = (const float*)d_in[4];
    const float* Wihb  = (const float*)d_in[5];
    const float* Whhb  = (const float*)d_in[6];
    const float* bb    = (const float*)d_in[7];
    const float* fc1W  = (const float*)d_in[8];
    const float* fc1b  = (const float*)d_in[9];
    const float* clsW  = (const float*)d_in[10];
    const float* clsb  = (const float*)d_in[11];
    const float* trans = (const float*)d_in[12];
    float* out = (float*)d_out;

    cudaFuncSetAttribute(k_lstm, cudaFuncAttributeMaxDynamicSharedMemorySize,
                         LSTM_SMEM_BYTES);
    cudaFuncSetAttribute(k_fc, cudaFuncAttributeMaxDynamicSharedMemorySize,
                         FC_SMEM_FLOATS * sizeof(float));

    k_xproj<<<dim3(16, 128), 256>>>(x, emb, Wihf, Wihb, bf, bb);
    k_lstm<<<128, 256, LSTM_SMEM_BYTES>>>(Whhf, Whhb);
    k_fc<<<128, 256, FC_SMEM_FLOATS * sizeof(float)>>>(fc1W, fc1b, clsW, clsb);
    k_viterbi<<<BB, 32>>>(trans, out);
}

// round 6
// speedup vs baseline: 1.0048x; 1.0048x over previous
#include <cuda_runtime.h>
#include <math.h>
#include <stdint.h>

// ---------------- problem constants ----------------
#define BB 64
#define TT 256
#define EE 300
#define HH 256
#define G4 1024          // 4*H
#define NLBL 17
#define LTOT 19
#define START_LBL 17
#define END_LBL 18
#define LOW_POT (-10000.0f)

typedef unsigned long long u64;

// ---------------- packed f32x2 helpers (Blackwell, .b64 regs) ----------------
__device__ __forceinline__ u64 fdup(float x) {
    u64 r; asm("mov.b64 %0,{%1,%1};" : "=l"(r) : "f"(x)); return r;
}
__device__ __forceinline__ void fma2(u64& a, u64 m, u64 b) {
    asm("fma.rn.f32x2 %0,%1,%2,%0;" : "+l"(a) : "l"(m), "l"(b));
}
__device__ __forceinline__ void add2(u64& a, u64 b) {
    asm("add.rn.f32x2 %0,%0,%1;" : "+l"(a) : "l"(b));
}
__device__ __forceinline__ float2 f2lo(u64 v) {
    float2 r; asm("mov.b64 {%0,%1},%2;" : "=f"(r.x), "=f"(r.y) : "l"(v)); return r;
}
__device__ __forceinline__ u64 pack64(unsigned lo, unsigned hi) {
    u64 r; asm("mov.b64 %0,{%1,%2};" : "=l"(r) : "r"(lo), "r"(hi)); return r;
}

// ---------------- device scratch ----------------
__device__ float g_xproj[(size_t)BB * TT * 2 * G4];   // [bt][2048] fwd 0..1023, bwd 1024..2047 (bias folded)
__device__ float g_hT[2][2][HH][BB];                  // [dir][buf][k][b] double-buffered recurrent state
__device__ float g_hall[(size_t)BB * TT * 2 * HH];    // [bt][512] concat(h_f, h_b)
__device__ float g_unary[(size_t)BB * TT * NLBL];     // [bt][17]
__device__ unsigned g_flag[2][64 * 8];                // per-block step flags, 32B padded

__device__ __forceinline__ float sigf(float x) { return 1.0f / (1.0f + expf(-x)); }

// ---------------- init ----------------
__global__ void k_init() {
    int i = blockIdx.x * blockDim.x + threadIdx.x;
    float* p = &g_hT[0][0][0][0];
    const int n = 2 * 2 * HH * BB;
    for (int l = i; l < n; l += gridDim.x * blockDim.x) p[l] = 0.0f;
    unsigned* f = &g_flag[0][0];
    for (int l = i; l < 2 * 64 * 8; l += gridDim.x * blockDim.x) f[l] = 0u;
}

// ---------------- kernel 1: embedding gather + x_proj GEMM ----------------
// 128x128 tile, 8x8 micro-tile via f32x2, k-tile 20 (300 = 15*20)
__global__ void k_xproj(const int* __restrict__ x, const float* __restrict__ emb,
                        const float* __restrict__ Wf, const float* __restrict__ Wb,
                        const float* __restrict__ bf, const float* __restrict__ bb) {
    __shared__ float As[20][128];
    __shared__ float Bs[20][128];
    __shared__ int toks[128];
    const int tid = threadIdx.x;
    const int m0 = blockIdx.y * 128;
    const int n0 = blockIdx.x * 128;
    const int tx = tid & 15;
    const int ty = tid >> 4;

    if (tid < 128) toks[tid] = x[m0 + tid];

    u64 acc2[8][4];
#pragma unroll
    for (int i = 0; i < 8; i++)
#pragma unroll
        for (int j = 0; j < 4; j++) acc2[i][j] = 0ull;
    __syncthreads();

    for (int k0 = 0; k0 < EE; k0 += 20) {
#pragma unroll
        for (int l = tid; l < 640; l += 256) {
            int kq = l >> 7, r = l & 127;
            float4 v = *(const float4*)&emb[(size_t)toks[r] * EE + k0 + kq * 4];
            As[kq * 4 + 0][r] = v.x; As[kq * 4 + 1][r] = v.y;
            As[kq * 4 + 2][r] = v.z; As[kq * 4 + 3][r] = v.w;
        }
#pragma unroll
        for (int l = tid; l < 640; l += 256) {
            int kq = l >> 7, r = l & 127;
            int g = n0 + r;
            const float* Wp = (g < G4) ? &Wf[(size_t)g * EE] : &Wb[(size_t)(g - G4) * EE];
            float4 v = *(const float4*)&Wp[k0 + kq * 4];
            Bs[kq * 4 + 0][r] = v.x; Bs[kq * 4 + 1][r] = v.y;
            Bs[kq * 4 + 2][r] = v.z; Bs[kq * 4 + 3][r] = v.w;
        }
        __syncthreads();
#pragma unroll
        for (int kk = 0; kk < 20; kk++) {
            float4 a0 = *(const float4*)&As[kk][ty * 8];
            float4 a1 = *(const float4*)&As[kk][ty * 8 + 4];
            ulonglong2 b01 = *(const ulonglong2*)&Bs[kk][tx * 8];
            ulonglong2 b23 = *(const ulonglong2*)&Bs[kk][tx * 8 + 4];
            float av[8] = {a0.x, a0.y, a0.z, a0.w, a1.x, a1.y, a1.z, a1.w};
#pragma unroll
            for (int i = 0; i < 8; i++) {
                u64 ad = fdup(av[i]);
                fma2(acc2[i][0], ad, b01.x);
                fma2(acc2[i][1], ad, b01.y);
                fma2(acc2[i][2], ad, b23.x);
                fma2(acc2[i][3], ad, b23.y);
            }
        }
        __syncthreads();
    }

    const int gc = n0 + tx * 8;
    float bias[8];
#pragma unroll
    for (int j = 0; j < 8; j++) {
        int g = gc + j;
        bias[j] = (g < G4) ? bf[g] : bb[g - G4];
    }
#pragma unroll
    for (int i = 0; i < 8; i++) {
        int row = m0 + ty * 8 + i;
        float2 p0 = f2lo(acc2[i][0]);
        float2 p1 = f2lo(acc2[i][1]);
        float2 p2 = f2lo(acc2[i][2]);
        float2 p3 = f2lo(acc2[i][3]);
        float4 v0 = make_float4(p0.x + bias[0], p0.y + bias[1], p1.x + bias[2], p1.y + bias[3]);
        float4 v1 = make_float4(p2.x + bias[4], p2.y + bias[5], p3.x + bias[6], p3.y + bias[7]);
        *(float4*)(&g_xproj[(size_t)row * 2048 + gc]) = v0;
        *(float4*)(&g_xproj[(size_t)row * 2048 + gc + 4]) = v1;
    }
}

// ---------------- kernel 2: persistent bidirectional LSTM ----------------
// 128 blocks: [0..63] fwd, [64..127] bwd. Block j owns hidden units [4j,4j+4).
// GEMV: 8 warps = 8 k-groups (range 32), lane = 8 batches x 4 cols, f32x2 FMA.
// Inter-block sync: per-block release flag + distributed acquire polling
// (no atomics -> no L2 atom-ALU serialization).
#define LSTM_SMEM_FLOATS (4096 + 16384 + 8192 + 1024)
__global__ void k_lstm(const float* __restrict__ Whf, const float* __restrict__ Whb) {
    extern __shared__ float sm[];
    float* Ws2 = sm;                        // [k][16]      4096 floats
    float* hs  = sm + 4096;                 // [k][64]      16384 floats
    u64*   red = (u64*)(sm + 4096 + 16384); // [8][512] u64 (8192 floats)
    float* gs  = sm + 4096 + 16384 + 8192;  // [s][64][4]   1024 floats

    const int bid = blockIdx.x;
    const int d = bid >> 6;
    const int j = bid & 63;
    const int hu0 = j * 4;
    const int tid = threadIdx.x;
    const float* Wh = d ? Whb : Whf;

    // Ws2[k*16+c] = Wh[(s*256+hu0+q)*256 + k], c = s*4+q
#pragma unroll
    for (int l = tid; l < 4096; l += 256) {
        int c = l >> 8;
        int k = l & 255;
        int s = c >> 2, q = c & 3;
        Ws2[k * 16 + c] = Wh[(size_t)(s * HH + hu0 + q) * HH + k];
    }

    // GEMV roles
    const int kg = tid >> 5;
    const int wi = tid & 31;
    const int c4 = (wi & 3) * 4;
    const int b8 = (wi >> 2) * 8;
    const int kbeg = kg * 32;

    // reducer roles: 2 packed outputs (c, batch-pair) per thread
    const int oid0 = tid * 2, oid1 = tid * 2 + 1;
    const int rc0 = oid0 >> 5, rb0 = (oid0 & 31) * 2;
    const int rc1 = oid1 >> 5, rb1 = (oid1 & 31) * 2;
    const size_t xcol0 = (size_t)d * G4 + (size_t)(rc0 >> 2) * HH + hu0 + (rc0 & 3);
    const size_t xcol1 = (size_t)d * G4 + (size_t)(rc1 >> 2) * HH + hu0 + (rc1 & 3);
    const int g0 = (rc0 >> 2) * 256 + (rc0 & 3);
    const int g1 = (rc1 >> 2) * 256 + (rc1 & 3);

    // elementwise role
    const int eb = tid & 63;
    const int eu = tid >> 6;
    float creg = 0.0f;
    __syncthreads();

    for (int step = 0; step < TT; step++) {
        const int t = d ? (TT - 1 - step) : step;
        const float* hb = &g_hT[d][step & 1][0][0];
        float* hw = &g_hT[d][(step & 1) ^ 1][0][0];

        // x-projection prefetch
        float x00 = __ldcg(&g_xproj[((size_t)(rb0 + 0) * TT + t) * 2048 + xcol0]);
        float x01 = __ldcg(&g_xproj[((size_t)(rb0 + 1) * TT + t) * 2048 + xcol0]);
        float x10 = __ldcg(&g_xproj[((size_t)(rb1 + 0) * TT + t) * 2048 + xcol1]);
        float x11 = __ldcg(&g_xproj[((size_t)(rb1 + 1) * TT + t) * 2048 + xcol1]);

        // stage h_prev into SMEM
        {
            const float4* hb4 = (const float4*)hb;
            float4* hs4 = (float4*)hs;
#pragma unroll
            for (int l = tid; l < 4096; l += 256) hs4[l] = __ldcg(hb4 + l);
        }
        __syncthreads();

        // GEMV partial over this warp's k range: 8 batches x 4 cols
        u64 acc2[4][4];
#pragma unroll
        for (int bp = 0; bp < 4; bp++)
#pragma unroll
            for (int ci = 0; ci < 4; ci++) acc2[bp][ci] = 0ull;
#pragma unroll 4
        for (int k = kbeg; k < kbeg + 32; k++) {
            ulonglong2 h01 = *(const ulonglong2*)&hs[k * 64 + b8];
            ulonglong2 h23 = *(const ulonglong2*)&hs[k * 64 + b8 + 4];
            float4 w4 = *(const float4*)&Ws2[k * 16 + c4];
            u64 w0 = fdup(w4.x), w1 = fdup(w4.y), w2 = fdup(w4.z), w3 = fdup(w4.w);
            fma2(acc2[0][0], h01.x, w0); fma2(acc2[0][1], h01.x, w1);
            fma2(acc2[0][2], h01.x, w2); fma2(acc2[0][3], h01.x, w3);
            fma2(acc2[1][0], h01.y, w0); fma2(acc2[1][1], h01.y, w1);
            fma2(acc2[1][2], h01.y, w2); fma2(acc2[1][3], h01.y, w3);
            fma2(acc2[2][0], h23.x, w0); fma2(acc2[2][1], h23.x, w1);
            fma2(acc2[2][2], h23.x, w2); fma2(acc2[2][3], h23.x, w3);
            fma2(acc2[3][0], h23.y, w0); fma2(acc2[3][1], h23.y, w1);
            fma2(acc2[3][2], h23.y, w2); fma2(acc2[3][3], h23.y, w3);
        }
#pragma unroll
        for (int ci = 0; ci < 4; ci++)
#pragma unroll
            for (int bp = 0; bp < 4; bp++)
                red[kg * 512 + (c4 + ci) * 32 + (b8 >> 1) + bp] = acc2[bp][ci];
        __syncthreads();

        // reduce 8 partials + add x-projection -> gate values
        {
            u64 s0 = red[oid0];
            u64 s1 = red[oid1];
#pragma unroll
            for (int g2 = 1; g2 < 8; g2++) {
                add2(s0, red[g2 * 512 + oid0]);
                add2(s1, red[g2 * 512 + oid1]);
            }
            float2 f0 = f2lo(s0), f1 = f2lo(s1);
            gs[g0 + (rb0 + 0) * 4] = f0.x + x00;
            gs[g0 + (rb0 + 1) * 4] = f0.y + x01;
            gs[g1 + (rb1 + 0) * 4] = f1.x + x10;
            gs[g1 + (rb1 + 1) * 4] = f1.y + x11;
        }
        __syncthreads();

        // elementwise LSTM cell
        {
            float iv = gs[0 * 256 + eb * 4 + eu];
            float fv = gs[1 * 256 + eb * 4 + eu];
            float gv = gs[2 * 256 + eb * 4 + eu];
            float ov = gs[3 * 256 + eb * 4 + eu];
            float cc = sigf(fv) * creg + sigf(iv) * tanhf(gv);
            creg = cc;
            float hh = sigf(ov) * tanhf(cc);
            hw[(hu0 + eu) * BB + eb] = hh;
            g_hall[((size_t)eb * TT + t) * 512 + d * HH + hu0 + eu] = hh;
        }
        __syncthreads();

        // barrier: release own flag, acquire-poll all 64 (no atomics)
        if (tid == 0) {
            asm volatile("st.release.gpu.u32 [%0], %1;"
                         :: "l"(&g_flag[d][j * 8]), "r"((unsigned)(step + 1)) : "memory");
        }
        if (tid < 64) {
            unsigned v;
            const unsigned* fp = &g_flag[d][tid * 8];
            do {
                asm volatile("ld.acquire.gpu.u32 %0, [%1];" : "=r"(v) : "l"(fp) : "memory");
            } while (v <= (unsigned)step);
        }
        __syncthreads();
    }
}

// ---------------- kernel 3: fused fc1(relu) + classifier ----------------
// k-tile 32 (16 tiles, halved sync count vs k-tile 16)
#define FC_SMEM_FLOATS (128 * 130)
__global__ void k_fc(const float* __restrict__ fc1W, const float* __restrict__ fc1b,
                     const float* __restrict__ clsW, const float* __restrict__ clsb) {
    __shared__ float As[32][128];
    __shared__ float Bs[32][128];
    extern __shared__ float inter[];   // [128][130]
    const int tid = threadIdx.x;
    const int m0 = blockIdx.x * 128;
    const int tr = tid >> 4;
    const int tc = tid & 15;

    u64 acc2[8][4];
#pragma unroll
    for (int i = 0; i < 8; i++)
#pragma unroll
        for (int jj = 0; jj < 4; jj++) acc2[i][jj] = 0ull;

    for (int k0 = 0; k0 < 512; k0 += 32) {
#pragma unroll
        for (int l = tid; l < 1024; l += 256) {
            int kq = l >> 7, r = l & 127;
            float4 v = *(const float4*)&g_hall[(size_t)(m0 + r) * 512 + k0 + kq * 4];
            As[kq * 4 + 0][r] = v.x; As[kq * 4 + 1][r] = v.y;
            As[kq * 4 + 2][r] = v.z; As[kq * 4 + 3][r] = v.w;
        }
#pragma unroll
        for (int l = tid; l < 1024; l += 256) {
            int kq = l >> 7, r = l & 127;
            float4 v = *(const float4*)&fc1W[(size_t)r * 512 + k0 + kq * 4];
            Bs[kq * 4 + 0][r] = v.x; Bs[kq * 4 + 1][r] = v.y;
            Bs[kq * 4 + 2][r] = v.z; Bs[kq * 4 + 3][r] = v.w;
        }
        __syncthreads();
#pragma unroll
        for (int kk = 0; kk < 32; kk++) {
            float4 a0 = *(const float4*)&As[kk][tr * 8];
            float4 a1 = *(const float4*)&As[kk][tr * 8 + 4];
            ulonglong2 b01 = *(const ulonglong2*)&Bs[kk][tc * 8];
            ulonglong2 b23 = *(const ulonglong2*)&Bs[kk][tc * 8 + 4];
            float av[8] = {a0.x, a0.y, a0.z, a0.w, a1.x, a1.y, a1.z, a1.w};
#pragma unroll
            for (int i = 0; i < 8; i++) {
                u64 ad = fdup(av[i]);
                fma2(acc2[i][0], ad, b01.x);
                fma2(acc2[i][1], ad, b01.y);
                fma2(acc2[i][2], ad, b23.x);
                fma2(acc2[i][3], ad, b23.y);
            }
        }
        __syncthreads();
    }
#pragma unroll
    for (int i = 0; i < 8; i++) {
        int r = tr * 8 + i;
#pragma unroll
        for (int jj = 0; jj < 4; jj++) {
            int n = tc * 8 + jj * 2;
            float2 p = f2lo(acc2[i][jj]);
            float v0 = p.x + fc1b[n];
            float v1 = p.y + fc1b[n + 1];
            inter[r * 130 + n]     = v0 > 0.0f ? v0 : 0.0f;
            inter[r * 130 + n + 1] = v1 > 0.0f ? v1 : 0.0f;
        }
    }
    __syncthreads();

    for (int idx = tid; idx < 128 * NLBL; idx += 256) {
        int r = idx / NLBL, lab = idx - r * NLBL;
        const u64* w2 = (const u64*)(clsW + (size_t)lab * 128);
        const u64* i2 = (const u64*)(inter + r * 130);
        u64 s2 = 0ull;
#pragma unroll 8
        for (int k = 0; k < 64; k++) fma2(s2, i2[k], w2[k]);
        float2 p = f2lo(s2);
        g_unary[(size_t)(m0 + r) * NLBL + lab] = clsb[lab] + p.x + p.y;
    }
}

// ---------------- kernel 4: Viterbi decode ----------------
// trans row in registers; candidates as sortable u64 keys (value bits high,
// 255-prev low => ties pick smaller prev = first-occurrence argmax); max tree.
__global__ void k_viterbi(const float* __restrict__ trans, float* __restrict__ out) {
    const int b = blockIdx.x;
    const int jl = threadIdx.x;
    __shared__ float sc[2][LTOT];
    __shared__ unsigned char bp[TT][LTOT];

    float trj[LTOT];
    if (jl < LTOT) {
#pragma unroll
        for (int p = 0; p < LTOT; p++) trj[p] = trans[jl * LTOT + p];
        sc[0][jl] = (jl == START_LBL) ? 0.0f : LOW_POT;
    }
    __syncwarp();

    const float* un = g_unary + (size_t)b * TT * NLBL;
    for (int t = 0; t < TT; t++) {
        const int cur = t & 1;
        if (jl < LTOT) {
            u64 key[20];
#pragma unroll
            for (int p = 0; p < LTOT; p++) {
                float v = sc[cur][p] + trj[p];
                unsigned vb = __float_as_uint(v);
                vb ^= (unsigned)(((int)vb) >> 31) | 0x80000000u;
                key[p] = pack64(255u - p, vb);
            }
            key[19] = 0ull;
            // max tree over 20
#pragma unroll
            for (int i = 0; i < 10; i++) key[i] = key[i] > key[i + 10] ? key[i] : key[i + 10];
#pragma unroll
            for (int i = 0; i < 5; i++) key[i] = key[i] > key[i + 5] ? key[i] : key[i + 5];
            key[0] = key[0] > key[3] ? key[0] : key[3];
            key[1] = key[1] > key[4] ? key[1] : key[4];
            key[0] = key[0] > key[1] ? key[0] : key[1];
            key[0] = key[0] > key[2] ? key[0] : key[2];
            unsigned pi = 255u - (unsigned)(key[0] & 0xffu);
            unsigned vb = (unsigned)(key[0] >> 32);
            vb = (vb & 0x80000000u) ? (vb ^ 0x80000000u) : ~vb;
            float mv = __uint_as_float(vb);
            float u = (jl < NLBL) ? __ldg(&un[t * NLBL + jl]) : LOW_POT;
            sc[cur ^ 1][jl] = mv + u;
            bp[t][jl] = (unsigned char)pi;
        }
        __syncwarp();
    }
    if (jl == 0) {
        float best = -3.4e38f;
        int bi = 0;
        for (int l = 0; l < LTOT; l++) {
            float v = sc[0][l] + trans[END_LBL * LTOT + l];
            if (v > best) { best = v; bi = l; }
        }
        out[b] = best;
        int lab = bi;
        for (int t = TT - 1; t >= 0; t--) {
            out[BB + b * TT + t] = (float)lab;
            lab = bp[t][lab];
        }
    }
}

// ---------------- launch ----------------
extern "C" void kernel_launch(void* const* d_in, const int* in_sizes, int n_in,
                              void* d_out, int out_size) {
    const int*   x     = (const int*)d_in[0];
    const float* emb   = (const float*)d_in[1];
    const float* Wihf  = (const float*)d_in[2];
    const float* Whhf  = (const float*)d_in[3];
    const float* bf    = (const float*)d_in[4];
    const float* Wihb  = (const float*)d_in[5];
    const float* Whhb  = (const float*)d_in[6];
    const float* bb    = (const float*)d_in[7];
    const float* fc1W  = (const float*)d_in[8];
    const float* fc1b  = (const float*)d_in[9];
    const float* clsW  = (const float*)d_in[10];
    const float* clsb  = (const float*)d_in[11];
    const float* trans = (const float*)d_in[12];
    float* out = (float*)d_out;

    cudaFuncSetAttribute(k_lstm, cudaFuncAttributeMaxDynamicSharedMemorySize,
                         LSTM_SMEM_FLOATS * sizeof(float));
    cudaFuncSetAttribute(k_fc, cudaFuncAttributeMaxDynamicSharedMemorySize,
                         FC_SMEM_FLOATS * sizeof(float));

    k_init<<<32, 256>>>();
    k_xproj<<<dim3(16, 128), 256>>>(x, emb, Wihf, Wihb, bf, bb);
    k_lstm<<<128, 256, LSTM_SMEM_FLOATS * sizeof(float)>>>(Whhf, Whhb);
    k_fc<<<128, 256, FC_SMEM_FLOATS * sizeof(float)>>>(fc1W, fc1b, clsW, clsb);
    k_viterbi<<<BB, 32>>>(trans, out);
}